// round 7
// baseline (speedup 1.0000x reference)
#include <cuda_runtime.h>

// FiniteDifference: x [B=4, T=16, H=128, W=128, C=16] fp32
// out = concat(dy (d/dH), dx (d/dW), dz (d/dT)); central diff, zero pad.
//
// R7: best-known structure (R1/R3 fused, 1 float4/thread, traffic-optimal
// ~201 MB compulsory writes with input L2-resident) with block=512 so each
// CTA emits 8 KB-contiguous segments per output stream (half as many
// distinct write fronts in flight). T-loads (longest reuse distance) issue
// first. Model: pure-write DRAM floor ~5.3 TB/s -> ~38 us kernel.

#define N4_TOTAL (4 * 16 * 128 * 128 * 4)  // 4,194,304 float4 elems per output

__device__ __forceinline__ float4 sub4(float4 a, float4 b) {
    return make_float4(a.x - b.x, a.y - b.y, a.z - b.z, a.w - b.w);
}

__global__ void __launch_bounds__(512)
fd_kernel(const float4* __restrict__ x, float4* __restrict__ out)
{
    int i = blockIdx.x * 512 + threadIdx.x;

    int w = (i >> 2)  & 127;
    int h = (i >> 9)  & 127;
    int t = (i >> 16) & 15;

    const float4 zero = make_float4(0.f, 0.f, 0.f, 0.f);

    // T first: farthest addresses (+-1 MiB), longest L2 reuse window.
    float4 tp = (t < 15)  ? x[i + 65536] : zero;
    float4 tm = (t > 0)   ? x[i - 65536] : zero;
    float4 hp = (h < 127) ? x[i + 512]   : zero;
    float4 hm = (h > 0)   ? x[i - 512]   : zero;
    float4 wp = (w < 127) ? x[i + 4]     : zero;
    float4 wm = (w > 0)   ? x[i - 4]     : zero;

    __stcs(&out[i],                sub4(hp, hm));  // dy
    __stcs(&out[i + N4_TOTAL],     sub4(wp, wm));  // dx
    __stcs(&out[i + 2 * N4_TOTAL], sub4(tp, tm));  // dz
}

extern "C" void kernel_launch(void* const* d_in, const int* in_sizes, int n_in,
                              void* d_out, int out_size)
{
    const float4* x = (const float4*)d_in[0];
    float4* out = (float4*)d_out;

    fd_kernel<<<N4_TOTAL / 512, 512>>>(x, out);
}

// round 8
// speedup vs baseline: 1.0036x; 1.0036x over previous
#include <cuda_runtime.h>

// FiniteDifference: x [B=4, T=16, H=128, W=128, C=16] fp32
// out = concat(dy (d/dH), dx (d/dW), dz (d/dT)); central diff, zero pad.
//
// FINAL (R8): fused 1-float4/thread structure — established as roofline over
// R1-R7: traffic-optimal (~201 MB compulsory writes, input L2-resident,
// measured DRAM ~= compulsory), write-drain-limited at ~5.3 TB/s which is
// path/pattern-independent (STG == __stcs == v8 == TMA bulk == axis-split).
// T-loads issue first (longest reuse distance); each output stored as soon
// as its operands arrive to minimize register live ranges.

#define N4_TOTAL (4 * 16 * 128 * 128 * 4)  // 4,194,304 float4 elems per output

__device__ __forceinline__ float4 sub4(float4 a, float4 b) {
    return make_float4(a.x - b.x, a.y - b.y, a.z - b.z, a.w - b.w);
}

__global__ void __launch_bounds__(256)
fd_kernel(const float4* __restrict__ x, float4* __restrict__ out)
{
    int i = blockIdx.x * blockDim.x + threadIdx.x;

    int w = (i >> 2)  & 127;
    int h = (i >> 9)  & 127;
    int t = (i >> 16) & 15;

    const float4 zero = make_float4(0.f, 0.f, 0.f, 0.f);

    float4 tp = (t < 15)  ? x[i + 65536] : zero;
    float4 tm = (t > 0)   ? x[i - 65536] : zero;
    float4 hp = (h < 127) ? x[i + 512]   : zero;
    float4 hm = (h > 0)   ? x[i - 512]   : zero;
    float4 wp = (w < 127) ? x[i + 4]     : zero;
    float4 wm = (w > 0)   ? x[i - 4]     : zero;

    __stcs(&out[i + 2 * N4_TOTAL], sub4(tp, tm));  // dz
    __stcs(&out[i],                sub4(hp, hm));  // dy
    __stcs(&out[i + N4_TOTAL],     sub4(wp, wm));  // dx
}

extern "C" void kernel_launch(void* const* d_in, const int* in_sizes, int n_in,
                              void* d_out, int out_size)
{
    const float4* x = (const float4*)d_in[0];
    float4* out = (float4*)d_out;

    fd_kernel<<<N4_TOTAL / 256, 256>>>(x, out);
}